// round 1
// baseline (speedup 1.0000x reference)
#include <cuda_runtime.h>
#include <cuda_bf16.h>
#include <cstdint>
#include <cstddef>

// ---------------------------------------------------------------------------
// MambaSequenceClassifier: B=8, L=1024, D_MODEL=256, D_INNER=512, D_STATE=16,
// D_CONV=4, DT_RANK=16, N_LAYERS=2.  All fp32.
// ---------------------------------------------------------------------------

#define B_SZ    8
#define L_SZ    1024
#define DM      256
#define DI      512
#define DS      16
#define DCNV    4
#define DR      16
#define NT      (B_SZ * L_SZ)        // 8192 tokens
#define NCHUNK  16
#define CLEN    (L_SZ / NCHUNK)      // 64
#define EPSF    1e-5f

// ---------------- device scratch (no allocation allowed) -------------------
__device__ float g_X    [NT * DM];        // residual stream
__device__ float g_XN   [NT * DM];        // rmsnorm output
__device__ float g_XZ   [NT * 2 * DI];    // in_proj output [xi | z]
__device__ float g_XI   [NT * DI];        // conv + silu output (u)
__device__ float g_DBC  [NT * 64];        // x_proj output, padded stride 64
__device__ float g_DELTA[NT * DI];
__device__ float g_Y    [NT * DI];
__device__ float g_HC   [B_SZ * NCHUNK * DI * DS];  // chunk-local final states
__device__ float g_PC   [B_SZ * NCHUNK * DI * DS];  // chunk cumprod(dA)
__device__ float g_HIN  [B_SZ * NCHUNK * DI * DS];  // chunk carry-in states
__device__ float g_XPW  [DI * 64];        // padded x_proj weights [512,64]

// ---------------------------------------------------------------------------
// rmsnorm: one warp per 256-wide row
// ---------------------------------------------------------------------------
__global__ void rmsnorm_k(const float* __restrict__ X, const float* __restrict__ w,
                          float* __restrict__ XN)
{
    int warp = threadIdx.x >> 5, lane = threadIdx.x & 31;
    size_t row = (size_t)blockIdx.x * 8 + warp;
    const float* xr = X + row * DM;
    float v[8];
    float ss = 0.f;
#pragma unroll
    for (int i = 0; i < 8; i++) { v[i] = xr[lane + 32 * i]; ss += v[i] * v[i]; }
#pragma unroll
    for (int o = 16; o; o >>= 1) ss += __shfl_xor_sync(0xffffffffu, ss, o);
    float rs = rsqrtf(ss * (1.f / DM) + EPSF);
    float* yr = XN + row * DM;
#pragma unroll
    for (int i = 0; i < 8; i++) yr[lane + 32 * i] = v[i] * rs * w[lane + 32 * i];
}

// ---------------------------------------------------------------------------
// Generic tiled SGEMM: C[M,N] (+)= op(A)[M,K] * Bw[K,N]
// BM=128, BK=16, TM=8; BN/TN template (128/8 or 64/4), 256 threads.
// GATED: A element = A[m,k] * silu(G[m,k]);  RESID: C += acc.
// All dims assumed divisible by tile sizes (true for this problem).
// ---------------------------------------------------------------------------
#define GBM 128
#define GBK 16

template<int BN, int TN, bool GATED, bool RESID>
__global__ void __launch_bounds__(256)
gemm_k(const float* __restrict__ A, const float* __restrict__ G,
       const float* __restrict__ Bw, float* __restrict__ C,
       int K, int lda, int ldg, int ldb, int ldc)
{
    __shared__ float As[GBK][GBM];
    __shared__ float Bs[GBK][BN];

    const int tid = threadIdx.x;
    const int bn  = blockIdx.x, bm = blockIdx.y;
    const int tx  = tid & 15, ty = tid >> 4;

    float acc[8][TN];
#pragma unroll
    for (int i = 0; i < 8; i++)
#pragma unroll
        for (int j = 0; j < TN; j++) acc[i][j] = 0.f;

    const float* Aptr = A + (size_t)bm * GBM * lda;
    const float* Gptr = G + (size_t)bm * GBM * ldg;   // only used if GATED
    const float* Bptr = Bw + (size_t)bn * BN;

    for (int k0 = 0; k0 < K; k0 += GBK) {
        // --- A tile: 128x16 floats = 512 float4, 2 per thread, store transposed
#pragma unroll
        for (int q = 0; q < 2; q++) {
            int f  = tid + q * 256;
            int r  = f >> 2;
            int c4 = (f & 3) * 4;
            float4 v = *(const float4*)(Aptr + (size_t)r * lda + k0 + c4);
            if (GATED) {
                float4 g = *(const float4*)(Gptr + (size_t)r * ldg + k0 + c4);
                v.x *= g.x / (1.f + __expf(-g.x));
                v.y *= g.y / (1.f + __expf(-g.y));
                v.z *= g.z / (1.f + __expf(-g.z));
                v.w *= g.w / (1.f + __expf(-g.w));
            }
            As[c4 + 0][r] = v.x; As[c4 + 1][r] = v.y;
            As[c4 + 2][r] = v.z; As[c4 + 3][r] = v.w;
        }
        // --- B tile: 16 x BN floats
#pragma unroll
        for (int q = 0; q < (GBK * BN) / (4 * 256); q++) {
            int f = tid + q * 256;
            int r = f / (BN / 4);
            int c = (f % (BN / 4)) * 4;
            *(float4*)(&Bs[r][c]) = *(const float4*)(Bptr + (size_t)(k0 + r) * ldb + c);
        }
        __syncthreads();

#pragma unroll
        for (int kk = 0; kk < GBK; kk++) {
            float ra[8], rb[TN];
#pragma unroll
            for (int i = 0; i < 8; i++) ra[i] = As[kk][ty * 8 + i];
#pragma unroll
            for (int j = 0; j < TN; j++) rb[j] = Bs[kk][tx * TN + j];
#pragma unroll
            for (int i = 0; i < 8; i++)
#pragma unroll
                for (int j = 0; j < TN; j++) acc[i][j] += ra[i] * rb[j];
        }
        __syncthreads();
    }

    float* Cp = C + (size_t)(bm * GBM + ty * 8) * ldc + bn * BN + tx * TN;
#pragma unroll
    for (int i = 0; i < 8; i++) {
#pragma unroll
        for (int j = 0; j < TN; j++) {
            float v = acc[i][j];
            if (RESID) v += Cp[(size_t)i * ldc + j];
            Cp[(size_t)i * ldc + j] = v;
        }
    }
}

// ---------------------------------------------------------------------------
// causal depthwise conv (width 4) + bias + silu.  Reads xi half of XZ.
// grid (DI/128, L/128, B), block 128
// ---------------------------------------------------------------------------
__global__ void conv_silu_k(const float* __restrict__ XZ, const float* __restrict__ cw,
                            const float* __restrict__ cb, float* __restrict__ XI)
{
    int d  = blockIdx.x * 128 + threadIdx.x;
    int b  = blockIdx.z;
    int t0 = blockIdx.y * 128;

    float w0 = cw[d * 4 + 0], w1 = cw[d * 4 + 1];
    float w2 = cw[d * 4 + 2], w3 = cw[d * 4 + 3];
    float bias = cb[d];

    const float* base = XZ + (size_t)b * L_SZ * (2 * DI) + d;
    float v0 = (t0 - 3 >= 0) ? base[(size_t)(t0 - 3) * (2 * DI)] : 0.f;
    float v1 = (t0 - 2 >= 0) ? base[(size_t)(t0 - 2) * (2 * DI)] : 0.f;
    float v2 = (t0 - 1 >= 0) ? base[(size_t)(t0 - 1) * (2 * DI)] : 0.f;

    float* out = XI + ((size_t)b * L_SZ + t0) * DI + d;
    for (int i = 0; i < 128; i++) {
        float v3 = base[(size_t)(t0 + i) * (2 * DI)];
        float y  = w0 * v0 + w1 * v1 + w2 * v2 + w3 * v3 + bias;
        y = y / (1.f + __expf(-y));
        out[(size_t)i * DI] = y;
        v0 = v1; v1 = v2; v2 = v3;
    }
}

// ---------------------------------------------------------------------------
// pad x_proj weights [512,48] -> [512,64] (zeros in cols 48..63)
// ---------------------------------------------------------------------------
__global__ void pad_k(const float* __restrict__ w, float* __restrict__ wp)
{
    int idx = blockIdx.x * 1024 + threadIdx.x;
    int r = idx >> 6, c = idx & 63;
    wp[idx] = (c < 48) ? w[r * 48 + c] : 0.f;
}

// ---------------------------------------------------------------------------
// delta = softplus(dt_r @ dtw + dtb).  grid (DI/256, NT), block 256
// ---------------------------------------------------------------------------
__global__ void delta_k(const float* __restrict__ DBC, const float* __restrict__ dtw,
                        const float* __restrict__ dtb, float* __restrict__ DELTA)
{
    __shared__ float sr[DR];
    size_t m = blockIdx.y;
    int d = blockIdx.x * 256 + threadIdx.x;
    if (threadIdx.x < DR) sr[threadIdx.x] = DBC[m * 64 + threadIdx.x];
    __syncthreads();
    float acc = dtb[d];
#pragma unroll
    for (int r = 0; r < DR; r++) acc += sr[r] * dtw[r * DI + d];
    float sp = (acc > 0.f) ? acc + log1pf(__expf(-acc)) : log1pf(__expf(acc));
    DELTA[m * DI + d] = sp;
}

// ---------------------------------------------------------------------------
// selective scan, chunked.  Pass 1: chunk-local final state H and cumprod P.
// grid (DI/128, NCHUNK, B), block 128.  One thread owns (b, chunk, d) x 16 states.
// Fast path: if A[d,n] == A[d,0]*(n+1) (true for this dataset: A_n = -(n+1)),
// dA_n = w^(n+1) with a single __expf; exact fallback otherwise.
// ---------------------------------------------------------------------------
__global__ void __launch_bounds__(128)
scan1_k(const float* __restrict__ DELTA, const float* __restrict__ U,
        const float* __restrict__ DBC, const float* __restrict__ alog,
        float* __restrict__ HC, float* __restrict__ PC)
{
    __shared__ float sB[CLEN][DS];
    int d = blockIdx.x * 128 + threadIdx.x;
    int c = blockIdx.y, b = blockIdx.z;
    size_t m0 = (size_t)b * L_SZ + (size_t)c * CLEN;

    for (int j = threadIdx.x; j < CLEN * DS; j += 128) {
        int i = j >> 4, n = j & 15;
        sB[i][n] = DBC[(m0 + i) * 64 + 16 + n];
    }

    float an[DS];
#pragma unroll
    for (int n = 0; n < DS; n++) an[n] = -__expf(alog[(size_t)d * DS + n]);
    float a0 = an[0];
    bool fast = true;
#pragma unroll
    for (int n = 1; n < DS; n++)
        if (fabsf(an[n] - a0 * (n + 1)) > 1e-4f * fabsf(an[n])) fast = false;
    __syncthreads();

    float h[DS], p[DS];
#pragma unroll
    for (int n = 0; n < DS; n++) { h[n] = 0.f; p[n] = 1.f; }

    const float* dp = DELTA + m0 * DI + d;
    const float* up = U     + m0 * DI + d;

    if (fast) {
        for (int t = 0; t < CLEN; t++) {
            float dl = dp[(size_t)t * DI];
            float du = dl * up[(size_t)t * DI];
            float e1 = __expf(dl * a0);
            float dA = e1;
#pragma unroll
            for (int n = 0; n < DS; n++) {
                h[n] = dA * h[n] + du * sB[t][n];
                p[n] *= dA;
                dA *= e1;
            }
        }
    } else {
        for (int t = 0; t < CLEN; t++) {
            float dl = dp[(size_t)t * DI];
            float du = dl * up[(size_t)t * DI];
#pragma unroll
            for (int n = 0; n < DS; n++) {
                float dA = __expf(dl * an[n]);
                h[n] = dA * h[n] + du * sB[t][n];
                p[n] *= dA;
            }
        }
    }

    size_t o = (((size_t)b * NCHUNK + c) * DI + d) * DS;
#pragma unroll
    for (int n = 0; n < DS; n++) { HC[o + n] = h[n]; PC[o + n] = p[n]; }
}

// ---------------------------------------------------------------------------
// combine: sequential over chunks (16 steps).  grid (DI*DS/1024, B), block 1024
// ---------------------------------------------------------------------------
__global__ void combine_k(const float* __restrict__ HC, const float* __restrict__ PC,
                          float* __restrict__ HIN)
{
    int b = blockIdx.y;
    int idx = blockIdx.x * 1024 + threadIdx.x;  // d*16+n
    float hin = 0.f;
    for (int c = 0; c < NCHUNK; c++) {
        size_t o = ((size_t)b * NCHUNK + c) * (DI * DS) + idx;
        HIN[o] = hin;
        hin = PC[o] * hin + HC[o];
    }
}

// ---------------------------------------------------------------------------
// Pass 2: full scan per chunk with carry-in, writes y (+ u*D_skip)
// ---------------------------------------------------------------------------
__global__ void __launch_bounds__(128)
scan2_k(const float* __restrict__ DELTA, const float* __restrict__ U,
        const float* __restrict__ DBC, const float* __restrict__ alog,
        const float* __restrict__ dsk, const float* __restrict__ HIN,
        float* __restrict__ Y)
{
    __shared__ float sB[CLEN][DS];
    __shared__ float sC[CLEN][DS];
    int d = blockIdx.x * 128 + threadIdx.x;
    int c = blockIdx.y, b = blockIdx.z;
    size_t m0 = (size_t)b * L_SZ + (size_t)c * CLEN;

    for (int j = threadIdx.x; j < CLEN * DS; j += 128) {
        int i = j >> 4, n = j & 15;
        sB[i][n] = DBC[(m0 + i) * 64 + 16 + n];
        sC[i][n] = DBC[(m0 + i) * 64 + 32 + n];
    }

    float an[DS];
#pragma unroll
    for (int n = 0; n < DS; n++) an[n] = -__expf(alog[(size_t)d * DS + n]);
    float a0 = an[0];
    bool fast = true;
#pragma unroll
    for (int n = 1; n < DS; n++)
        if (fabsf(an[n] - a0 * (n + 1)) > 1e-4f * fabsf(an[n])) fast = false;
    __syncthreads();

    float h[DS];
    size_t o = (((size_t)b * NCHUNK + c) * DI + d) * DS;
#pragma unroll
    for (int n = 0; n < DS; n++) h[n] = HIN[o + n];

    float Dd = dsk[d];
    const float* dp = DELTA + m0 * DI + d;
    const float* up = U     + m0 * DI + d;
    float* yp = Y + m0 * DI + d;

    if (fast) {
        for (int t = 0; t < CLEN; t++) {
            float dl = dp[(size_t)t * DI];
            float u  = up[(size_t)t * DI];
            float du = dl * u;
            float e1 = __expf(dl * a0);
            float dA = e1;
            float y = 0.f;
#pragma unroll
            for (int n = 0; n < DS; n++) {
                h[n] = dA * h[n] + du * sB[t][n];
                y += h[n] * sC[t][n];
                dA *= e1;
            }
            yp[(size_t)t * DI] = y + u * Dd;
        }
    } else {
        for (int t = 0; t < CLEN; t++) {
            float dl = dp[(size_t)t * DI];
            float u  = up[(size_t)t * DI];
            float du = dl * u;
            float y = 0.f;
#pragma unroll
            for (int n = 0; n < DS; n++) {
                float dA = __expf(dl * an[n]);
                h[n] = dA * h[n] + du * sB[t][n];
                y += h[n] * sC[t][n];
            }
            yp[(size_t)t * DI] = y + u * Dd;
        }
    }
}

// ---------------------------------------------------------------------------
// final: rmsnorm(last token) . fc_w + fc_b per batch.  1 block, warp=batch.
// ---------------------------------------------------------------------------
__global__ void final_k(const float* __restrict__ X, const float* __restrict__ nfw,
                        const float* __restrict__ fcw, const float* __restrict__ fcb,
                        float* __restrict__ out)
{
    int b = threadIdx.x >> 5, lane = threadIdx.x & 31;
    const float* xr = X + ((size_t)b * L_SZ + (L_SZ - 1)) * DM;
    float v[8];
    float ss = 0.f;
#pragma unroll
    for (int i = 0; i < 8; i++) { v[i] = xr[lane + 32 * i]; ss += v[i] * v[i]; }
#pragma unroll
    for (int o = 16; o; o >>= 1) ss += __shfl_xor_sync(0xffffffffu, ss, o);
    float rs = rsqrtf(ss * (1.f / DM) + EPSF);
    float acc = 0.f;
#pragma unroll
    for (int i = 0; i < 8; i++) {
        int j = lane + 32 * i;
        acc += v[i] * rs * nfw[j] * fcw[j];
    }
#pragma unroll
    for (int o = 16; o; o >>= 1) acc += __shfl_xor_sync(0xffffffffu, acc, o);
    if (lane == 0) out[b] = acc + fcb[0];
}

// ---------------------------------------------------------------------------
extern "C" void kernel_launch(void* const* d_in, const int* in_sizes, int n_in,
                              void* d_out, int out_size)
{
    (void)in_sizes; (void)n_in; (void)out_size;
    const float* x    = (const float*)d_in[0];
    const float* nw   = (const float*)d_in[1];
    const float* ipw  = (const float*)d_in[2];
    const float* cw   = (const float*)d_in[3];
    const float* cb   = (const float*)d_in[4];
    const float* xpw  = (const float*)d_in[5];
    const float* dtw  = (const float*)d_in[6];
    const float* dtb  = (const float*)d_in[7];
    const float* alog = (const float*)d_in[8];
    const float* dsk  = (const float*)d_in[9];
    const float* opw  = (const float*)d_in[10];
    const float* nfw  = (const float*)d_in[11];
    const float* fcw  = (const float*)d_in[12];
    const float* fcb  = (const float*)d_in[13];

    float *X, *XN, *XZ, *XI, *DBC, *DELTA, *Y, *HC, *PC, *HIN, *XPW;
    cudaGetSymbolAddress((void**)&X,     g_X);
    cudaGetSymbolAddress((void**)&XN,    g_XN);
    cudaGetSymbolAddress((void**)&XZ,    g_XZ);
    cudaGetSymbolAddress((void**)&XI,    g_XI);
    cudaGetSymbolAddress((void**)&DBC,   g_DBC);
    cudaGetSymbolAddress((void**)&DELTA, g_DELTA);
    cudaGetSymbolAddress((void**)&Y,     g_Y);
    cudaGetSymbolAddress((void**)&HC,    g_HC);
    cudaGetSymbolAddress((void**)&PC,    g_PC);
    cudaGetSymbolAddress((void**)&HIN,   g_HIN);
    cudaGetSymbolAddress((void**)&XPW,   g_XPW);

    cudaMemcpyAsync(X, x, (size_t)NT * DM * sizeof(float), cudaMemcpyDeviceToDevice);

    for (int l = 0; l < 2; l++) {
        rmsnorm_k<<<NT / 8, 256>>>(X, nw + (size_t)l * DM, XN);

        // in_proj: [8192,256] @ [256,1024] -> XZ
        gemm_k<128, 8, false, false><<<dim3(2 * DI / 128, NT / 128), 256>>>(
            XN, nullptr, ipw + (size_t)l * DM * 2 * DI, XZ,
            DM, DM, 0, 2 * DI, 2 * DI);

        conv_silu_k<<<dim3(DI / 128, L_SZ / 128, B_SZ), 128>>>(
            XZ, cw + (size_t)l * DI * DCNV, cb + (size_t)l * DI, XI);

        pad_k<<<(DI * 64) / 1024, 1024>>>(xpw + (size_t)l * DI * 48, XPW);

        // x_proj: [8192,512] @ [512,64pad] -> DBC (stride 64)
        gemm_k<64, 4, false, false><<<dim3(1, NT / 128), 256>>>(
            XI, nullptr, XPW, DBC, DI, DI, 0, 64, 64);

        delta_k<<<dim3(DI / 256, NT), 256>>>(
            DBC, dtw + (size_t)l * DR * DI, dtb + (size_t)l * DI, DELTA);

        scan1_k<<<dim3(DI / 128, NCHUNK, B_SZ), 128>>>(
            DELTA, XI, DBC, alog + (size_t)l * DI * DS, HC, PC);

        combine_k<<<dim3((DI * DS) / 1024, B_SZ), 1024>>>(HC, PC, HIN);

        scan2_k<<<dim3(DI / 128, NCHUNK, B_SZ), 128>>>(
            DELTA, XI, DBC, alog + (size_t)l * DI * DS,
            dsk + (size_t)l * DI, HIN, Y);

        // out_proj (gated, residual): X += (Y * silu(z)) @ opw
        gemm_k<128, 8, true, true><<<dim3(DM / 128, NT / 128), 256>>>(
            Y, XZ + DI, opw + (size_t)l * DI * DM, X,
            DI, DI, 2 * DI, DM, DM);
    }

    final_k<<<1, 256>>>(X, nfw, fcw, fcb, (float*)d_out);
}

// round 2
// speedup vs baseline: 1.1067x; 1.1067x over previous
#include <cuda_runtime.h>
#include <cuda_bf16.h>
#include <cstdint>
#include <cstddef>

// ---------------------------------------------------------------------------
// MambaSequenceClassifier: B=8, L=1024, D_MODEL=256, D_INNER=512, D_STATE=16,
// D_CONV=4, DT_RANK=16, N_LAYERS=2.  All fp32.
// Round 2: FFMA2 (fma.rn.f32x2) GEMM inner product + double-buffered tiles.
// ---------------------------------------------------------------------------

#define B_SZ    8
#define L_SZ    1024
#define DM      256
#define DI      512
#define DS      16
#define DCNV    4
#define DR      16
#define NT      (B_SZ * L_SZ)        // 8192 tokens
#define NCHUNK  16
#define CLEN    (L_SZ / NCHUNK)      // 64
#define EPSF    1e-5f

// ---------------- device scratch (no allocation allowed) -------------------
__device__ float g_X    [NT * DM];
__device__ float g_XN   [NT * DM];
__device__ float g_XZ   [NT * 2 * DI];
__device__ float g_XI   [NT * DI];
__device__ float g_DBC  [NT * 64];
__device__ float g_DELTA[NT * DI];
__device__ float g_Y    [NT * DI];
__device__ float g_HC   [B_SZ * NCHUNK * DI * DS];
__device__ float g_PC   [B_SZ * NCHUNK * DI * DS];
__device__ float g_HIN  [B_SZ * NCHUNK * DI * DS];
__device__ float g_XPW  [DI * 64];

// ---------------------------------------------------------------------------
// rmsnorm: one warp per 256-wide row
// ---------------------------------------------------------------------------
__global__ void rmsnorm_k(const float* __restrict__ X, const float* __restrict__ w,
                          float* __restrict__ XN)
{
    int warp = threadIdx.x >> 5, lane = threadIdx.x & 31;
    size_t row = (size_t)blockIdx.x * 8 + warp;
    const float* xr = X + row * DM;
    float v[8];
    float ss = 0.f;
#pragma unroll
    for (int i = 0; i < 8; i++) { v[i] = xr[lane + 32 * i]; ss += v[i] * v[i]; }
#pragma unroll
    for (int o = 16; o; o >>= 1) ss += __shfl_xor_sync(0xffffffffu, ss, o);
    float rs = rsqrtf(ss * (1.f / DM) + EPSF);
    float* yr = XN + row * DM;
#pragma unroll
    for (int i = 0; i < 8; i++) yr[lane + 32 * i] = v[i] * rs * w[lane + 32 * i];
}

// ---------------------------------------------------------------------------
// Tiled SGEMM with packed f32x2 FMAs + double-buffered SMEM.
// C[M,N] (+)= op(A)[M,K] * Bw[K,N]
// 256 threads; tx in [0,16) covers BN=16*TN columns; ty in [0,16) covers
// BM=16*TM rows.  GATED: A element = A[m,k]*silu(G[m,k]); RESID: C += acc.
// ---------------------------------------------------------------------------
#define GBK 16

template<int BM, int BN, int TM, int TN, bool GATED, bool RESID>
__global__ void __launch_bounds__(256)
gemm_k(const float* __restrict__ A, const float* __restrict__ G,
       const float* __restrict__ Bw, float* __restrict__ C,
       int K, int lda, int ldg, int ldb, int ldc)
{
    static_assert(16 * TM == BM && 16 * TN == BN, "tile mismatch");
    constexpr int QA = (BM * GBK) / (4 * 256);   // float4 A-loads per thread
    constexpr int QB = (BN * GBK) / (4 * 256);   // float4 B-loads per thread

    __shared__ __align__(16) float As[2][GBK][BM];
    __shared__ __align__(16) float Bs[2][GBK][BN];

    const int tid = threadIdx.x;
    const int bn  = blockIdx.x, bm = blockIdx.y;
    const int tx  = tid & 15, ty = tid >> 4;

    unsigned long long acc[TM][TN / 2];
#pragma unroll
    for (int i = 0; i < TM; i++)
#pragma unroll
        for (int j = 0; j < TN / 2; j++) acc[i][j] = 0ull;

    const float* Aptr = A + (size_t)bm * BM * lda;
    const float* Gptr = GATED ? (G + (size_t)bm * BM * ldg) : nullptr;
    const float* Bptr = Bw + (size_t)bn * BN;

    float4 pa[QA], pb[QB];

    // ---- prologue: load tile 0 into regs ----
#pragma unroll
    for (int q = 0; q < QA; q++) {
        int f = tid + q * 256, r = f >> 2, c4 = (f & 3) * 4;
        float4 v = *(const float4*)(Aptr + (size_t)r * lda + c4);
        if (GATED) {
            float4 g = *(const float4*)(Gptr + (size_t)r * ldg + c4);
            v.x *= g.x / (1.f + __expf(-g.x));
            v.y *= g.y / (1.f + __expf(-g.y));
            v.z *= g.z / (1.f + __expf(-g.z));
            v.w *= g.w / (1.f + __expf(-g.w));
        }
        pa[q] = v;
    }
#pragma unroll
    for (int q = 0; q < QB; q++) {
        int f = tid + q * 256;
        int r = f / (BN / 4), c = (f % (BN / 4)) * 4;
        pb[q] = *(const float4*)(Bptr + (size_t)r * ldb + c);
    }
#pragma unroll
    for (int q = 0; q < QA; q++) {
        int f = tid + q * 256, r = f >> 2, c4 = (f & 3) * 4;
        As[0][c4 + 0][r] = pa[q].x; As[0][c4 + 1][r] = pa[q].y;
        As[0][c4 + 2][r] = pa[q].z; As[0][c4 + 3][r] = pa[q].w;
    }
#pragma unroll
    for (int q = 0; q < QB; q++) {
        int f = tid + q * 256;
        int r = f / (BN / 4), c = (f % (BN / 4)) * 4;
        *(float4*)(&Bs[0][r][c]) = pb[q];
    }
    __syncthreads();

    const int nit = K / GBK;
    for (int it = 0; it < nit; it++) {
        const int buf = it & 1;
        const bool more = (it + 1 < nit);

        // ---- prefetch next K-tile into registers (latency hidden by math) --
        if (more) {
            const int k0 = (it + 1) * GBK;
#pragma unroll
            for (int q = 0; q < QA; q++) {
                int f = tid + q * 256, r = f >> 2, c4 = (f & 3) * 4;
                float4 v = *(const float4*)(Aptr + (size_t)r * lda + k0 + c4);
                if (GATED) {
                    float4 g = *(const float4*)(Gptr + (size_t)r * ldg + k0 + c4);
                    v.x *= g.x / (1.f + __expf(-g.x));
                    v.y *= g.y / (1.f + __expf(-g.y));
                    v.z *= g.z / (1.f + __expf(-g.z));
                    v.w *= g.w / (1.f + __expf(-g.w));
                }
                pa[q] = v;
            }
#pragma unroll
            for (int q = 0; q < QB; q++) {
                int f = tid + q * 256;
                int r = f / (BN / 4), c = (f % (BN / 4)) * 4;
                pb[q] = *(const float4*)(Bptr + (size_t)(k0 + r) * ldb + c);
            }
        }

        // ---- compute on current buffer ----
#pragma unroll
        for (int kk = 0; kk < GBK; kk++) {
            // A fragment: TM floats, each duplicated into a f32x2 pair
            unsigned long long rap[TM];
#pragma unroll
            for (int v4 = 0; v4 < TM / 4; v4++) {
                float4 a = *(const float4*)(&As[buf][kk][ty * TM + v4 * 4]);
                asm("mov.b64 %0, {%1, %1};" : "=l"(rap[v4 * 4 + 0]) : "f"(a.x));
                asm("mov.b64 %0, {%1, %1};" : "=l"(rap[v4 * 4 + 1]) : "f"(a.y));
                asm("mov.b64 %0, {%1, %1};" : "=l"(rap[v4 * 4 + 2]) : "f"(a.z));
                asm("mov.b64 %0, {%1, %1};" : "=l"(rap[v4 * 4 + 3]) : "f"(a.w));
            }
            // B fragment: TN/2 packed pairs (consecutive columns)
            unsigned long long rbp[TN / 2];
#pragma unroll
            for (int v2 = 0; v2 < TN / 4; v2++) {
                ulonglong2 b = *(const ulonglong2*)(&Bs[buf][kk][tx * TN + v2 * 4]);
                rbp[v2 * 2 + 0] = b.x;
                rbp[v2 * 2 + 1] = b.y;
            }
#pragma unroll
            for (int i = 0; i < TM; i++)
#pragma unroll
                for (int j = 0; j < TN / 2; j++)
                    asm("fma.rn.f32x2 %0, %1, %2, %0;"
                        : "+l"(acc[i][j]) : "l"(rap[i]), "l"(rbp[j]));
        }

        // ---- stage next tile into the other buffer ----
        if (more) {
            const int nb = buf ^ 1;
#pragma unroll
            for (int q = 0; q < QA; q++) {
                int f = tid + q * 256, r = f >> 2, c4 = (f & 3) * 4;
                As[nb][c4 + 0][r] = pa[q].x; As[nb][c4 + 1][r] = pa[q].y;
                As[nb][c4 + 2][r] = pa[q].z; As[nb][c4 + 3][r] = pa[q].w;
            }
#pragma unroll
            for (int q = 0; q < QB; q++) {
                int f = tid + q * 256;
                int r = f / (BN / 4), c = (f % (BN / 4)) * 4;
                *(float4*)(&Bs[nb][r][c]) = pb[q];
            }
            __syncthreads();
        }
    }

    // ---- epilogue ----
    float* Cp = C + (size_t)(bm * BM + ty * TM) * ldc + bn * BN + tx * TN;
#pragma unroll
    for (int i = 0; i < TM; i++) {
#pragma unroll
        for (int j = 0; j < TN / 2; j++) {
            float lo, hi;
            asm("mov.b64 {%0, %1}, %2;" : "=f"(lo), "=f"(hi) : "l"(acc[i][j]));
            if (RESID) {
                lo += Cp[(size_t)i * ldc + 2 * j + 0];
                hi += Cp[(size_t)i * ldc + 2 * j + 1];
            }
            Cp[(size_t)i * ldc + 2 * j + 0] = lo;
            Cp[(size_t)i * ldc + 2 * j + 1] = hi;
        }
    }
}

// ---------------------------------------------------------------------------
// causal depthwise conv (width 4) + bias + silu
// ---------------------------------------------------------------------------
__global__ void conv_silu_k(const float* __restrict__ XZ, const float* __restrict__ cw,
                            const float* __restrict__ cb, float* __restrict__ XI)
{
    int d  = blockIdx.x * 128 + threadIdx.x;
    int b  = blockIdx.z;
    int t0 = blockIdx.y * 128;

    float w0 = cw[d * 4 + 0], w1 = cw[d * 4 + 1];
    float w2 = cw[d * 4 + 2], w3 = cw[d * 4 + 3];
    float bias = cb[d];

    const float* base = XZ + (size_t)b * L_SZ * (2 * DI) + d;
    float v0 = (t0 - 3 >= 0) ? base[(size_t)(t0 - 3) * (2 * DI)] : 0.f;
    float v1 = (t0 - 2 >= 0) ? base[(size_t)(t0 - 2) * (2 * DI)] : 0.f;
    float v2 = (t0 - 1 >= 0) ? base[(size_t)(t0 - 1) * (2 * DI)] : 0.f;

    float* out = XI + ((size_t)b * L_SZ + t0) * DI + d;
    for (int i = 0; i < 128; i++) {
        float v3 = base[(size_t)(t0 + i) * (2 * DI)];
        float y  = w0 * v0 + w1 * v1 + w2 * v2 + w3 * v3 + bias;
        y = y / (1.f + __expf(-y));
        out[(size_t)i * DI] = y;
        v0 = v1; v1 = v2; v2 = v3;
    }
}

// ---------------------------------------------------------------------------
__global__ void pad_k(const float* __restrict__ w, float* __restrict__ wp)
{
    int idx = blockIdx.x * 1024 + threadIdx.x;
    int r = idx >> 6, c = idx & 63;
    wp[idx] = (c < 48) ? w[r * 48 + c] : 0.f;
}

// ---------------------------------------------------------------------------
// delta = softplus(dt_r @ dtw + dtb)
// ---------------------------------------------------------------------------
__global__ void delta_k(const float* __restrict__ DBC, const float* __restrict__ dtw,
                        const float* __restrict__ dtb, float* __restrict__ DELTA)
{
    __shared__ float sr[DR];
    size_t m = blockIdx.y;
    int d = blockIdx.x * 256 + threadIdx.x;
    if (threadIdx.x < DR) sr[threadIdx.x] = DBC[m * 64 + threadIdx.x];
    __syncthreads();
    float acc = dtb[d];
#pragma unroll
    for (int r = 0; r < DR; r++) acc += sr[r] * dtw[r * DI + d];
    float sp = (acc > 0.f) ? acc + log1pf(__expf(-acc)) : log1pf(__expf(acc));
    DELTA[m * DI + d] = sp;
}

// ---------------------------------------------------------------------------
// selective scan, chunked (2-pass + combine).  Fast path exploits
// A[d,n] = A[d,0]*(n+1) (true for this dataset) -> one __expf per step.
// ---------------------------------------------------------------------------
__global__ void __launch_bounds__(128)
scan1_k(const float* __restrict__ DELTA, const float* __restrict__ U,
        const float* __restrict__ DBC, const float* __restrict__ alog,
        float* __restrict__ HC, float* __restrict__ PC)
{
    __shared__ float sB[CLEN][DS];
    int d = blockIdx.x * 128 + threadIdx.x;
    int c = blockIdx.y, b = blockIdx.z;
    size_t m0 = (size_t)b * L_SZ + (size_t)c * CLEN;

    for (int j = threadIdx.x; j < CLEN * DS; j += 128) {
        int i = j >> 4, n = j & 15;
        sB[i][n] = DBC[(m0 + i) * 64 + 16 + n];
    }

    float an[DS];
#pragma unroll
    for (int n = 0; n < DS; n++) an[n] = -__expf(alog[(size_t)d * DS + n]);
    float a0 = an[0];
    bool fast = true;
#pragma unroll
    for (int n = 1; n < DS; n++)
        if (fabsf(an[n] - a0 * (n + 1)) > 1e-4f * fabsf(an[n])) fast = false;
    __syncthreads();

    float h[DS], p[DS];
#pragma unroll
    for (int n = 0; n < DS; n++) { h[n] = 0.f; p[n] = 1.f; }

    const float* dp = DELTA + m0 * DI + d;
    const float* up = U     + m0 * DI + d;

    if (fast) {
        for (int t = 0; t < CLEN; t++) {
            float dl = dp[(size_t)t * DI];
            float du = dl * up[(size_t)t * DI];
            float e1 = __expf(dl * a0);
            float dA = e1;
#pragma unroll
            for (int n = 0; n < DS; n++) {
                h[n] = dA * h[n] + du * sB[t][n];
                p[n] *= dA;
                dA *= e1;
            }
        }
    } else {
        for (int t = 0; t < CLEN; t++) {
            float dl = dp[(size_t)t * DI];
            float du = dl * up[(size_t)t * DI];
#pragma unroll
            for (int n = 0; n < DS; n++) {
                float dA = __expf(dl * an[n]);
                h[n] = dA * h[n] + du * sB[t][n];
                p[n] *= dA;
            }
        }
    }

    size_t o = (((size_t)b * NCHUNK + c) * DI + d) * DS;
#pragma unroll
    for (int n = 0; n < DS; n++) { HC[o + n] = h[n]; PC[o + n] = p[n]; }
}

__global__ void combine_k(const float* __restrict__ HC, const float* __restrict__ PC,
                          float* __restrict__ HIN)
{
    int b = blockIdx.y;
    int idx = blockIdx.x * 1024 + threadIdx.x;
    float hin = 0.f;
    for (int c = 0; c < NCHUNK; c++) {
        size_t o = ((size_t)b * NCHUNK + c) * (DI * DS) + idx;
        HIN[o] = hin;
        hin = PC[o] * hin + HC[o];
    }
}

__global__ void __launch_bounds__(128)
scan2_k(const float* __restrict__ DELTA, const float* __restrict__ U,
        const float* __restrict__ DBC, const float* __restrict__ alog,
        const float* __restrict__ dsk, const float* __restrict__ HIN,
        float* __restrict__ Y)
{
    __shared__ float sB[CLEN][DS];
    __shared__ float sC[CLEN][DS];
    int d = blockIdx.x * 128 + threadIdx.x;
    int c = blockIdx.y, b = blockIdx.z;
    size_t m0 = (size_t)b * L_SZ + (size_t)c * CLEN;

    for (int j = threadIdx.x; j < CLEN * DS; j += 128) {
        int i = j >> 4, n = j & 15;
        sB[i][n] = DBC[(m0 + i) * 64 + 16 + n];
        sC[i][n] = DBC[(m0 + i) * 64 + 32 + n];
    }

    float an[DS];
#pragma unroll
    for (int n = 0; n < DS; n++) an[n] = -__expf(alog[(size_t)d * DS + n]);
    float a0 = an[0];
    bool fast = true;
#pragma unroll
    for (int n = 1; n < DS; n++)
        if (fabsf(an[n] - a0 * (n + 1)) > 1e-4f * fabsf(an[n])) fast = false;
    __syncthreads();

    float h[DS];
    size_t o = (((size_t)b * NCHUNK + c) * DI + d) * DS;
#pragma unroll
    for (int n = 0; n < DS; n++) h[n] = HIN[o + n];

    float Dd = dsk[d];
    const float* dp = DELTA + m0 * DI + d;
    const float* up = U     + m0 * DI + d;
    float* yp = Y + m0 * DI + d;

    if (fast) {
        for (int t = 0; t < CLEN; t++) {
            float dl = dp[(size_t)t * DI];
            float u  = up[(size_t)t * DI];
            float du = dl * u;
            float e1 = __expf(dl * a0);
            float dA = e1;
            float y = 0.f;
#pragma unroll
            for (int n = 0; n < DS; n++) {
                h[n] = dA * h[n] + du * sB[t][n];
                y += h[n] * sC[t][n];
                dA *= e1;
            }
            yp[(size_t)t * DI] = y + u * Dd;
        }
    } else {
        for (int t = 0; t < CLEN; t++) {
            float dl = dp[(size_t)t * DI];
            float u  = up[(size_t)t * DI];
            float du = dl * u;
            float y = 0.f;
#pragma unroll
            for (int n = 0; n < DS; n++) {
                float dA = __expf(dl * an[n]);
                h[n] = dA * h[n] + du * sB[t][n];
                y += h[n] * sC[t][n];
            }
            yp[(size_t)t * DI] = y + u * Dd;
        }
    }
}

// ---------------------------------------------------------------------------
__global__ void final_k(const float* __restrict__ X, const float* __restrict__ nfw,
                        const float* __restrict__ fcw, const float* __restrict__ fcb,
                        float* __restrict__ out)
{
    int b = threadIdx.x >> 5, lane = threadIdx.x & 31;
    const float* xr = X + ((size_t)b * L_SZ + (L_SZ - 1)) * DM;
    float v[8];
    float ss = 0.f;
#pragma unroll
    for (int i = 0; i < 8; i++) { v[i] = xr[lane + 32 * i]; ss += v[i] * v[i]; }
#pragma unroll
    for (int o = 16; o; o >>= 1) ss += __shfl_xor_sync(0xffffffffu, ss, o);
    float rs = rsqrtf(ss * (1.f / DM) + EPSF);
    float acc = 0.f;
#pragma unroll
    for (int i = 0; i < 8; i++) {
        int j = lane + 32 * i;
        acc += v[i] * rs * nfw[j] * fcw[j];
    }
#pragma unroll
    for (int o = 16; o; o >>= 1) acc += __shfl_xor_sync(0xffffffffu, acc, o);
    if (lane == 0) out[b] = acc + fcb[0];
}

// ---------------------------------------------------------------------------
extern "C" void kernel_launch(void* const* d_in, const int* in_sizes, int n_in,
                              void* d_out, int out_size)
{
    (void)in_sizes; (void)n_in; (void)out_size;
    const float* x    = (const float*)d_in[0];
    const float* nw   = (const float*)d_in[1];
    const float* ipw  = (const float*)d_in[2];
    const float* cw   = (const float*)d_in[3];
    const float* cb   = (const float*)d_in[4];
    const float* xpw  = (const float*)d_in[5];
    const float* dtw  = (const float*)d_in[6];
    const float* dtb  = (const float*)d_in[7];
    const float* alog = (const float*)d_in[8];
    const float* dsk  = (const float*)d_in[9];
    const float* opw  = (const float*)d_in[10];
    const float* nfw  = (const float*)d_in[11];
    const float* fcw  = (const float*)d_in[12];
    const float* fcb  = (const float*)d_in[13];

    float *X, *XN, *XZ, *XI, *DBC, *DELTA, *Y, *HC, *PC, *HIN, *XPW;
    cudaGetSymbolAddress((void**)&X,     g_X);
    cudaGetSymbolAddress((void**)&XN,    g_XN);
    cudaGetSymbolAddress((void**)&XZ,    g_XZ);
    cudaGetSymbolAddress((void**)&XI,    g_XI);
    cudaGetSymbolAddress((void**)&DBC,   g_DBC);
    cudaGetSymbolAddress((void**)&DELTA, g_DELTA);
    cudaGetSymbolAddress((void**)&Y,     g_Y);
    cudaGetSymbolAddress((void**)&HC,    g_HC);
    cudaGetSymbolAddress((void**)&PC,    g_PC);
    cudaGetSymbolAddress((void**)&HIN,   g_HIN);
    cudaGetSymbolAddress((void**)&XPW,   g_XPW);

    cudaMemcpyAsync(X, x, (size_t)NT * DM * sizeof(float), cudaMemcpyDeviceToDevice);

    for (int l = 0; l < 2; l++) {
        rmsnorm_k<<<NT / 8, 256>>>(X, nw + (size_t)l * DM, XN);

        // in_proj: [8192,256] @ [256,1024] -> XZ    grid (8, 64)
        gemm_k<128, 128, 8, 8, false, false><<<dim3(2 * DI / 128, NT / 128), 256>>>(
            XN, nullptr, ipw + (size_t)l * DM * 2 * DI, XZ,
            DM, DM, 0, 2 * DI, 2 * DI);

        conv_silu_k<<<dim3(DI / 128, L_SZ / 128, B_SZ), 128>>>(
            XZ, cw + (size_t)l * DI * DCNV, cb + (size_t)l * DI, XI);

        pad_k<<<(DI * 64) / 1024, 1024>>>(xpw + (size_t)l * DI * 48, XPW);

        // x_proj: [8192,512] @ [512,64pad] -> DBC   grid (1, 128)
        gemm_k<64, 64, 4, 4, false, false><<<dim3(1, NT / 64), 256>>>(
            XI, nullptr, XPW, DBC, DI, DI, 0, 64, 64);

        delta_k<<<dim3(DI / 256, NT), 256>>>(
            DBC, dtw + (size_t)l * DR * DI, dtb + (size_t)l * DI, DELTA);

        scan1_k<<<dim3(DI / 128, NCHUNK, B_SZ), 128>>>(
            DELTA, XI, DBC, alog + (size_t)l * DI * DS, HC, PC);

        combine_k<<<dim3((DI * DS) / 1024, B_SZ), 1024>>>(HC, PC, HIN);

        scan2_k<<<dim3(DI / 128, NCHUNK, B_SZ), 128>>>(
            DELTA, XI, DBC, alog + (size_t)l * DI * DS,
            dsk + (size_t)l * DI, HIN, Y);

        // out_proj (gated, residual): X += (Y * silu(z)) @ opw   grid (2, 64)
        gemm_k<128, 128, 8, 8, true, true><<<dim3(DM / 128, NT / 128), 256>>>(
            Y, XZ + DI, opw + (size_t)l * DI * DM, X,
            DI, DI, 2 * DI, DM, DM);
    }

    final_k<<<1, 256>>>(X, nfw, fcw, fcb, (float*)d_out);
}

// round 4
// speedup vs baseline: 1.4607x; 1.3199x over previous
#include <cuda_runtime.h>
#include <cuda_bf16.h>
#include <cstdint>
#include <cstddef>

// ---------------------------------------------------------------------------
// MambaSequenceClassifier: B=8, L=1024, D_MODEL=256, D_INNER=512, D_STATE=16,
// D_CONV=4, DT_RANK=16, N_LAYERS=2.
// Round 4: GEMMs on mma.sync (HMMA bf16, hi/lo 3-pass, fp32 accum).
// (tcgen05 is rejected by this build's compute_103 PTX target.)
// ---------------------------------------------------------------------------

#define B_SZ    8
#define L_SZ    1024
#define DM      256
#define DI      512
#define DS      16
#define DCNV    4
#define DR      16
#define NT      (B_SZ * L_SZ)        // 8192 tokens
#define NCHUNK  16
#define CLEN    (L_SZ / NCHUNK)      // 64
#define EPSF    1e-5f

// SW64 swizzle over 64-byte rows: off ^ (((off)>>3)&0x30)
#define SW64(o) ((o) ^ (((o) >> 3) & 0x30))

__device__ __forceinline__ uint32_t smem_to_u32(const void* p) {
    uint32_t a;
    asm("{ .reg .u64 t; cvta.to.shared.u64 t, %1; cvt.u32.u64 %0, t; }"
        : "=r"(a) : "l"(p));
    return a;
}
__device__ __forceinline__ void ldsm_x4(uint32_t (&r)[4], uint32_t addr) {
    asm volatile("ldmatrix.sync.aligned.m8n8.x4.shared.b16 {%0,%1,%2,%3}, [%4];"
        : "=r"(r[0]), "=r"(r[1]), "=r"(r[2]), "=r"(r[3]) : "r"(addr));
}
__device__ __forceinline__ void mma_bf16(float (&d)[4], const uint32_t (&a)[4],
                                         uint32_t b0, uint32_t b1) {
    asm volatile("mma.sync.aligned.m16n8k16.row.col.f32.bf16.bf16.f32 "
        "{%0,%1,%2,%3},{%4,%5,%6,%7},{%8,%9},{%0,%1,%2,%3};"
        : "+f"(d[0]), "+f"(d[1]), "+f"(d[2]), "+f"(d[3])
        : "r"(a[0]), "r"(a[1]), "r"(a[2]), "r"(a[3]), "r"(b0), "r"(b1));
}
__device__ __forceinline__ void split2(float x, __nv_bfloat16& hi, __nv_bfloat16& lo)
{
    hi = __float2bfloat16(x);
    lo = __float2bfloat16(x - __bfloat162float(hi));
}

// ---------------- device scratch (no allocation allowed) -------------------
__device__ float g_X    [NT * DM];
__device__ float g_XZ   [NT * 2 * DI];
__device__ float g_XI   [NT * DI];
__device__ float g_DBC  [NT * 64];
__device__ float g_DELTA[NT * DI];
__device__ float g_HC   [B_SZ * NCHUNK * DI * DS];
__device__ float g_PC   [B_SZ * NCHUNK * DI * DS];
__device__ float g_HIN  [B_SZ * NCHUNK * DI * DS];

__device__ __nv_bfloat16 g_XNh[NT * DM],  g_XNl[NT * DM];
__device__ __nv_bfloat16 g_XIh[NT * DI],  g_XIl[NT * DI];
__device__ __nv_bfloat16 g_YGh[NT * DI],  g_YGl[NT * DI];
__device__ __nv_bfloat16 g_Wih[1024 * DM], g_Wil[1024 * DM];   // in_proj  [1024 x 256]
__device__ __nv_bfloat16 g_Wxh[64 * DI],   g_Wxl[64 * DI];     // x_proj   [64 x 512]
__device__ __nv_bfloat16 g_Woh[DM * DI],   g_Wol[DM * DI];     // out_proj [256 x 512]

// ---------------------------------------------------------------------------
// weight repack: B[n][k] = W[k][n] (zero-pad rows n >= Norig), hi/lo bf16
// ---------------------------------------------------------------------------
__global__ void repack_k(const float* __restrict__ W, __nv_bfloat16* __restrict__ Bh,
                         __nv_bfloat16* __restrict__ Bl, int K, int Norig)
{
    int idx = blockIdx.x * 256 + threadIdx.x;
    int n = idx / K, k = idx % K;
    float v = (n < Norig) ? W[(size_t)k * Norig + n] : 0.f;
    __nv_bfloat16 hi, lo;
    split2(v, hi, lo);
    Bh[idx] = hi; Bl[idx] = lo;
}

// ---------------------------------------------------------------------------
// rmsnorm -> bf16 hi/lo (one warp per row)
// ---------------------------------------------------------------------------
__global__ void rmsnorm_k(const float* __restrict__ X, const float* __restrict__ w,
                          __nv_bfloat16* __restrict__ XNh, __nv_bfloat16* __restrict__ XNl)
{
    int warp = threadIdx.x >> 5, lane = threadIdx.x & 31;
    size_t row = (size_t)blockIdx.x * 8 + warp;
    const float* xr = X + row * DM;
    float v[8];
    float ss = 0.f;
#pragma unroll
    for (int i = 0; i < 8; i++) { v[i] = xr[lane + 32 * i]; ss += v[i] * v[i]; }
#pragma unroll
    for (int o = 16; o; o >>= 1) ss += __shfl_xor_sync(0xffffffffu, ss, o);
    float rs = rsqrtf(ss * (1.f / DM) + EPSF);
#pragma unroll
    for (int i = 0; i < 8; i++) {
        int j = lane + 32 * i;
        float y = v[i] * rs * w[j];
        __nv_bfloat16 hi, lo;
        split2(y, hi, lo);
        XNh[row * DM + j] = hi; XNl[row * DM + j] = lo;
    }
}

// ---------------------------------------------------------------------------
// HMMA GEMM: C[M,N](+)= (Ah+Al)[M,K] * (Bh+Bl)[N,K]^T, 3-pass hi/lo.
// CTA tile 128 x BN, BK=32.  8 warps.
//   BN=128: warp grid 2(m) x 4(n), warp tile 64x32
//   BN= 64: warp grid 4(m) x 2(n), warp tile 32x32
// smem: per-operand [rows][32] bf16, 64B rows, SW64 swizzle; conflict-free
// ldmatrix.x4 for A and B (B stored [n][k] -> col-major operand, no .trans).
// ---------------------------------------------------------------------------
template<int BN, bool RESID>
__global__ void __launch_bounds__(256)
mma_gemm_k(const __nv_bfloat16* __restrict__ Ah, const __nv_bfloat16* __restrict__ Al,
           const __nv_bfloat16* __restrict__ Bh, const __nv_bfloat16* __restrict__ Bl,
           float* __restrict__ C, int K, int ldc)
{
    constexpr int WM   = (BN == 128) ? 2 : 4;
    constexpr int MT   = 128 / WM;          // 64 or 32
    constexpr int NTT  = BN / (8 / WM);     // 32
    constexpr int MT16 = MT / 16;           // 4 or 2
    constexpr int NP   = NTT / 16;          // 2 (pairs of n8 tiles)
    constexpr int QA   = 2;                 // uint4 global loads per thread (A)
    constexpr int QB   = (BN * 4) / 256;    // 2 or 1

    __shared__ __align__(16) char sA[2][128 * 64];
    __shared__ __align__(16) char sB[2][BN * 64];

    const int tid = threadIdx.x, wid = tid >> 5, lane = tid & 31;
    const int wm = wid % WM, wn = wid / WM;
    const int bn = blockIdx.x, bm = blockIdx.y;

    const uint32_t sA0 = smem_to_u32(sA[0]), sA1 = smem_to_u32(sA[1]);
    const uint32_t sB0 = smem_to_u32(sB[0]), sB1 = smem_to_u32(sB[1]);

    float acc[MT16][4][4];
#pragma unroll
    for (int i = 0; i < MT16; i++)
#pragma unroll
        for (int j = 0; j < 4; j++)
#pragma unroll
            for (int q = 0; q < 4; q++) acc[i][j][q] = 0.f;

    // ldmatrix lane addressing (bytes within tile)
    const int a_row = lane & 15;
    const int a_seg = lane >> 4;                       // 0/1
    const int b_row = ((lane >> 4) << 3) | (lane & 7);
    const int b_seg = (lane >> 3) & 1;

    const int nkc = K / 32;
    for (int kc = 0; kc < nkc; kc++) {
        // ---- global -> smem (hi and lo tiles) ----
#pragma unroll
        for (int q = 0; q < QA; q++) {
            int f = tid + q * 256, r = f >> 2, s = f & 3;
            size_t go = (size_t)(bm * 128 + r) * K + kc * 32 + s * 8;
            uint32_t so = SW64(r * 64 + s * 16);
            *(uint4*)(sA[0] + so) = *(const uint4*)(Ah + go);
            *(uint4*)(sA[1] + so) = *(const uint4*)(Al + go);
        }
#pragma unroll
        for (int q = 0; q < QB; q++) {
            int f = tid + q * 256, r = f >> 2, s = f & 3;
            size_t go = (size_t)(bn * BN + r) * K + kc * 32 + s * 8;
            uint32_t so = SW64(r * 64 + s * 16);
            *(uint4*)(sB[0] + so) = *(const uint4*)(Bh + go);
            *(uint4*)(sB[1] + so) = *(const uint4*)(Bl + go);
        }
        __syncthreads();

        // ---- 3 passes: Ah*Bh, Ah*Bl, Al*Bh ----
#pragma unroll
        for (int p = 0; p < 3; p++) {
            const uint32_t pa = (p == 2) ? sA1 : sA0;
            const uint32_t pb = (p == 1) ? sB1 : sB0;
#pragma unroll
            for (int k16 = 0; k16 < 2; k16++) {
                uint32_t afr[MT16][4], bfr[NP][4];
#pragma unroll
                for (int mt = 0; mt < MT16; mt++) {
                    int row = wm * MT + mt * 16 + a_row;
                    ldsm_x4(afr[mt], pa + SW64(row * 64 + (k16 * 2 + a_seg) * 16));
                }
#pragma unroll
                for (int np = 0; np < NP; np++) {
                    int row = wn * NTT + np * 16 + b_row;
                    ldsm_x4(bfr[np], pb + SW64(row * 64 + (k16 * 2 + b_seg) * 16));
                }
#pragma unroll
                for (int mt = 0; mt < MT16; mt++)
#pragma unroll
                    for (int np = 0; np < NP; np++) {
                        mma_bf16(acc[mt][2 * np + 0], afr[mt], bfr[np][0], bfr[np][1]);
                        mma_bf16(acc[mt][2 * np + 1], afr[mt], bfr[np][2], bfr[np][3]);
                    }
            }
        }
        __syncthreads();
    }

    // ---- epilogue: direct register -> global ----
    const int r0 = bm * 128 + wm * MT + (lane >> 2);
    const int c0 = bn * BN + wn * NTT + (lane & 3) * 2;
#pragma unroll
    for (int mt = 0; mt < MT16; mt++) {
#pragma unroll
        for (int nt = 0; nt < 4; nt++) {
            int row = r0 + mt * 16;
            int col = c0 + nt * 8;
            float* p0 = C + (size_t)row * ldc + col;
            float* p1 = C + (size_t)(row + 8) * ldc + col;
            float2 v0 = make_float2(acc[mt][nt][0], acc[mt][nt][1]);
            float2 v1 = make_float2(acc[mt][nt][2], acc[mt][nt][3]);
            if (RESID) {
                float2 o0 = *(const float2*)p0, o1 = *(const float2*)p1;
                v0.x += o0.x; v0.y += o0.y; v1.x += o1.x; v1.y += o1.y;
            }
            *(float2*)p0 = v0;
            *(float2*)p1 = v1;
        }
    }
}

// ---------------------------------------------------------------------------
// causal depthwise conv (width 4) + bias + silu -> XI fp32 + bf16 hi/lo
// ---------------------------------------------------------------------------
__global__ void conv_silu_k(const float* __restrict__ XZ, const float* __restrict__ cw,
                            const float* __restrict__ cb, float* __restrict__ XI,
                            __nv_bfloat16* __restrict__ XIh, __nv_bfloat16* __restrict__ XIl)
{
    int d  = blockIdx.x * 128 + threadIdx.x;
    int b  = blockIdx.z;
    int t0 = blockIdx.y * 128;

    float w0 = cw[d * 4 + 0], w1 = cw[d * 4 + 1];
    float w2 = cw[d * 4 + 2], w3 = cw[d * 4 + 3];
    float bias = cb[d];

    const float* base = XZ + (size_t)b * L_SZ * (2 * DI) + d;
    float v0 = (t0 - 3 >= 0) ? base[(size_t)(t0 - 3) * (2 * DI)] : 0.f;
    float v1 = (t0 - 2 >= 0) ? base[(size_t)(t0 - 2) * (2 * DI)] : 0.f;
    float v2 = (t0 - 1 >= 0) ? base[(size_t)(t0 - 1) * (2 * DI)] : 0.f;

    size_t o = ((size_t)b * L_SZ + t0) * DI + d;
    for (int i = 0; i < 128; i++) {
        float v3 = base[(size_t)(t0 + i) * (2 * DI)];
        float y  = w0 * v0 + w1 * v1 + w2 * v2 + w3 * v3 + bias;
        y = y / (1.f + __expf(-y));
        XI[o + (size_t)i * DI] = y;
        __nv_bfloat16 hi, lo;
        split2(y, hi, lo);
        XIh[o + (size_t)i * DI] = hi;
        XIl[o + (size_t)i * DI] = lo;
        v0 = v1; v1 = v2; v2 = v3;
    }
}

// ---------------------------------------------------------------------------
// delta = softplus(dt_r @ dtw + dtb).  Weights in regs; dt_r tile in smem.
// ---------------------------------------------------------------------------
__global__ void __launch_bounds__(128)
delta_k(const float* __restrict__ DBC, const float* __restrict__ dtw,
        const float* __restrict__ dtb, float* __restrict__ DELTA)
{
    __shared__ float sr[64][DR];
    int d = blockIdx.x * 128 + threadIdx.x;
    size_t m0 = (size_t)blockIdx.y * 64;

    for (int i = threadIdx.x; i < 64 * DR; i += 128)
        sr[i >> 4][i & 15] = DBC[(m0 + (i >> 4)) * 64 + (i & 15)];

    float wt[DR];
#pragma unroll
    for (int r = 0; r < DR; r++) wt[r] = dtw[r * DI + d];
    float bias = dtb[d];
    __syncthreads();

    for (int t = 0; t < 64; t++) {
        float acc = bias;
#pragma unroll
        for (int r = 0; r < DR; r++) acc += sr[t][r] * wt[r];
        float sp = (acc > 0.f) ? acc + log1pf(__expf(-acc)) : log1pf(__expf(acc));
        DELTA[(m0 + t) * DI + d] = sp;
    }
}

// ---------------------------------------------------------------------------
// selective scan, chunked (2-pass + combine).
// ---------------------------------------------------------------------------
__global__ void __launch_bounds__(128)
scan1_k(const float* __restrict__ DELTA, const float* __restrict__ U,
        const float* __restrict__ DBC, const float* __restrict__ alog,
        float* __restrict__ HC, float* __restrict__ PC)
{
    __shared__ float sB[CLEN][DS];
    int d = blockIdx.x * 128 + threadIdx.x;
    int c = blockIdx.y, b = blockIdx.z;
    size_t m0 = (size_t)b * L_SZ + (size_t)c * CLEN;

    for (int j = threadIdx.x; j < CLEN * DS; j += 128) {
        int i = j >> 4, n = j & 15;
        sB[i][n] = DBC[(m0 + i) * 64 + 16 + n];
    }

    float an[DS];
#pragma unroll
    for (int n = 0; n < DS; n++) an[n] = -__expf(alog[(size_t)d * DS + n]);
    float a0 = an[0];
    bool fast = true;
#pragma unroll
    for (int n = 1; n < DS; n++)
        if (fabsf(an[n] - a0 * (n + 1)) > 1e-4f * fabsf(an[n])) fast = false;
    __syncthreads();

    float h[DS], p[DS];
#pragma unroll
    for (int n = 0; n < DS; n++) { h[n] = 0.f; p[n] = 1.f; }

    const float* dp = DELTA + m0 * DI + d;
    const float* up = U     + m0 * DI + d;

    if (fast) {
        for (int t = 0; t < CLEN; t++) {
            float dl = dp[(size_t)t * DI];
            float du = dl * up[(size_t)t * DI];
            float e1 = __expf(dl * a0);
            float dA = e1;
#pragma unroll
            for (int n = 0; n < DS; n++) {
                h[n] = dA * h[n] + du * sB[t][n];
                p[n] *= dA;
                dA *= e1;
            }
        }
    } else {
        for (int t = 0; t < CLEN; t++) {
            float dl = dp[(size_t)t * DI];
            float du = dl * up[(size_t)t * DI];
#pragma unroll
            for (int n = 0; n < DS; n++) {
                float dA = __expf(dl * an[n]);
                h[n] = dA * h[n] + du * sB[t][n];
                p[n] *= dA;
            }
        }
    }

    size_t o = (((size_t)b * NCHUNK + c) * DI + d) * DS;
#pragma unroll
    for (int n = 0; n < DS; n++) { HC[o + n] = h[n]; PC[o + n] = p[n]; }
}

__global__ void combine_k(const float* __restrict__ HC, const float* __restrict__ PC,
                          float* __restrict__ HIN)
{
    int b = blockIdx.y;
    int idx = blockIdx.x * 1024 + threadIdx.x;
    float hin = 0.f;
    for (int c = 0; c < NCHUNK; c++) {
        size_t o = ((size_t)b * NCHUNK + c) * (DI * DS) + idx;
        HIN[o] = hin;
        hin = PC[o] * hin + HC[o];
    }
}

// Pass 2 + fused gating:  out = (y + u*D) * silu(z)  ->  bf16 hi/lo
__global__ void __launch_bounds__(128)
scan2_k(const float* __restrict__ DELTA, const float* __restrict__ U,
        const float* __restrict__ DBC, const float* __restrict__ alog,
        const float* __restrict__ dsk, const float* __restrict__ HIN,
        const float* __restrict__ XZ,
        __nv_bfloat16* __restrict__ YGh, __nv_bfloat16* __restrict__ YGl)
{
    __shared__ float sB[CLEN][DS];
    __shared__ float sC[CLEN][DS];
    int d = blockIdx.x * 128 + threadIdx.x;
    int c = blockIdx.y, b = blockIdx.z;
    size_t m0 = (size_t)b * L_SZ + (size_t)c * CLEN;

    for (int j = threadIdx.x; j < CLEN * DS; j += 128) {
        int i = j >> 4, n = j & 15;
        sB[i][n] = DBC[(m0 + i) * 64 + 16 + n];
        sC[i][n] = DBC[(m0 + i) * 64 + 32 + n];
    }

    float an[DS];
#pragma unroll
    for (int n = 0; n < DS; n++) an[n] = -__expf(alog[(size_t)d * DS + n]);
    float a0 = an[0];
    bool fast = true;
#pragma unroll
    for (int n = 1; n < DS; n++)
        if (fabsf(an[n] - a0 * (n + 1)) > 1e-4f * fabsf(an[n])) fast = false;
    __syncthreads();

    float h[DS];
    size_t o = (((size_t)b * NCHUNK + c) * DI + d) * DS;
#pragma unroll
    for (int n = 0; n < DS; n++) h[n] = HIN[o + n];

    float Dd = dsk[d];
    const float* dp = DELTA + m0 * DI + d;
    const float* up = U     + m0 * DI + d;
    const float* zp = XZ + m0 * (2 * DI) + DI + d;

    for (int t = 0; t < CLEN; t++) {
        float dl = dp[(size_t)t * DI];
        float u  = up[(size_t)t * DI];
        float du = dl * u;
        float y = 0.f;
        if (fast) {
            float e1 = __expf(dl * a0);
            float dA = e1;
#pragma unroll
            for (int n = 0; n < DS; n++) {
                h[n] = dA * h[n] + du * sB[t][n];
                y += h[n] * sC[t][n];
                dA *= e1;
            }
        } else {
#pragma unroll
            for (int n = 0; n < DS; n++) {
                float dA = __expf(dl * an[n]);
                h[n] = dA * h[n] + du * sB[t][n];
                y += h[n] * sC[t][n];
            }
        }
        float z = zp[(size_t)t * (2 * DI)];
        float g = z / (1.f + __expf(-z));
        float out = (y + u * Dd) * g;
        __nv_bfloat16 hi, lo;
        split2(out, hi, lo);
        YGh[m0 * DI + (size_t)t * DI + d] = hi;
        YGl[m0 * DI + (size_t)t * DI + d] = lo;
    }
}

// ---------------------------------------------------------------------------
__global__ void final_k(const float* __restrict__ X, const float* __restrict__ nfw,
                        const float* __restrict__ fcw, const float* __restrict__ fcb,
                        float* __restrict__ out)
{
    int b = threadIdx.x >> 5, lane = threadIdx.x & 31;
    const float* xr = X + ((size_t)b * L_SZ + (L_SZ - 1)) * DM;
    float v[8];
    float ss = 0.f;
#pragma unroll
    for (int i = 0; i < 8; i++) { v[i] = xr[lane + 32 * i]; ss += v[i] * v[i]; }
#pragma unroll
    for (int o = 16; o; o >>= 1) ss += __shfl_xor_sync(0xffffffffu, ss, o);
    float rs = rsqrtf(ss * (1.f / DM) + EPSF);
    float acc = 0.f;
#pragma unroll
    for (int i = 0; i < 8; i++) {
        int j = lane + 32 * i;
        acc += v[i] * rs * nfw[j] * fcw[j];
    }
#pragma unroll
    for (int o = 16; o; o >>= 1) acc += __shfl_xor_sync(0xffffffffu, acc, o);
    if (lane == 0) out[b] = acc + fcb[0];
}

// ---------------------------------------------------------------------------
extern "C" void kernel_launch(void* const* d_in, const int* in_sizes, int n_in,
                              void* d_out, int out_size)
{
    (void)in_sizes; (void)n_in; (void)out_size;
    const float* x    = (const float*)d_in[0];
    const float* nw   = (const float*)d_in[1];
    const float* ipw  = (const float*)d_in[2];
    const float* cw   = (const float*)d_in[3];
    const float* cb   = (const float*)d_in[4];
    const float* xpw  = (const float*)d_in[5];
    const float* dtw  = (const float*)d_in[6];
    const float* dtb  = (const float*)d_in[7];
    const float* alog = (const float*)d_in[8];
    const float* dsk  = (const float*)d_in[9];
    const float* opw  = (const float*)d_in[10];
    const float* nfw  = (const float*)d_in[11];
    const float* fcw  = (const float*)d_in[12];
    const float* fcb  = (const float*)d_in[13];

    float *X, *XZ, *XI, *DBC, *DELTA, *HC, *PC, *HIN;
    __nv_bfloat16 *XNh, *XNl, *XIh, *XIl, *YGh, *YGl;
    __nv_bfloat16 *Wih, *Wil, *Wxh, *Wxl, *Woh, *Wol;
    cudaGetSymbolAddress((void**)&X,     g_X);
    cudaGetSymbolAddress((void**)&XZ,    g_XZ);
    cudaGetSymbolAddress((void**)&XI,    g_XI);
    cudaGetSymbolAddress((void**)&DBC,   g_DBC);
    cudaGetSymbolAddress((void**)&DELTA, g_DELTA);
    cudaGetSymbolAddress((void**)&HC,    g_HC);
    cudaGetSymbolAddress((void**)&PC,    g_PC);
    cudaGetSymbolAddress((void**)&HIN,   g_HIN);
    cudaGetSymbolAddress((void**)&XNh,   g_XNh);
    cudaGetSymbolAddress((void**)&XNl,   g_XNl);
    cudaGetSymbolAddress((void**)&XIh,   g_XIh);
    cudaGetSymbolAddress((void**)&XIl,   g_XIl);
    cudaGetSymbolAddress((void**)&YGh,   g_YGh);
    cudaGetSymbolAddress((void**)&YGl,   g_YGl);
    cudaGetSymbolAddress((void**)&Wih,   g_Wih);
    cudaGetSymbolAddress((void**)&Wil,   g_Wil);
    cudaGetSymbolAddress((void**)&Wxh,   g_Wxh);
    cudaGetSymbolAddress((void**)&Wxl,   g_Wxl);
    cudaGetSymbolAddress((void**)&Woh,   g_Woh);
    cudaGetSymbolAddress((void**)&Wol,   g_Wol);

    cudaMemcpyAsync(X, x, (size_t)NT * DM * sizeof(float), cudaMemcpyDeviceToDevice);

    for (int l = 0; l < 2; l++) {
        // weight repacks (transposed, hi/lo bf16)
        repack_k<<<(1024 * DM) / 256, 256>>>(ipw + (size_t)l * DM * 2 * DI, Wih, Wil, DM, 2 * DI);
        repack_k<<<(64 * DI) / 256, 256>>>(xpw + (size_t)l * DI * 48, Wxh, Wxl, DI, 48);
        repack_k<<<(DM * DI) / 256, 256>>>(opw + (size_t)l * DI * DM, Woh, Wol, DI, DM);

        rmsnorm_k<<<NT / 8, 256>>>(X, nw + (size_t)l * DM, XNh, XNl);

        // in_proj: [8192,256] x [256,1024] -> XZ
        mma_gemm_k<128, false><<<dim3(2 * DI / 128, NT / 128), 256>>>(
            XNh, XNl, Wih, Wil, XZ, DM, 2 * DI);

        conv_silu_k<<<dim3(DI / 128, L_SZ / 128, B_SZ), 128>>>(
            XZ, cw + (size_t)l * DI * DCNV, cb + (size_t)l * DI, XI, XIh, XIl);

        // x_proj: [8192,512] x [512,64pad] -> DBC
        mma_gemm_k<64, false><<<dim3(1, NT / 128), 256>>>(
            XIh, XIl, Wxh, Wxl, DBC, DI, 64);

        delta_k<<<dim3(DI / 128, NT / 64), 128>>>(
            DBC, dtw + (size_t)l * DR * DI, dtb + (size_t)l * DI, DELTA);

        scan1_k<<<dim3(DI / 128, NCHUNK, B_SZ), 128>>>(
            DELTA, XI, DBC, alog + (size_t)l * DI * DS, HC, PC);

        combine_k<<<dim3((DI * DS) / 1024, B_SZ), 1024>>>(HC, PC, HIN);

        scan2_k<<<dim3(DI / 128, NCHUNK, B_SZ), 128>>>(
            DELTA, XI, DBC, alog + (size_t)l * DI * DS,
            dsk + (size_t)l * DI, HIN, XZ, YGh, YGl);

        // out_proj (residual): X += YG @ opw
        mma_gemm_k<128, true><<<dim3(DM / 128, NT / 128), 256>>>(
            YGh, YGl, Woh, Wol, X, DI, DM);
    }

    final_k<<<1, 256>>>(X, nfw, fcw, fcb, (float*)d_out);
}